// round 12
// baseline (speedup 1.0000x reference)
#include <cuda_runtime.h>
#include <cstdint>

// Chamfer distance: ONE persistent kernel, 256 co-resident CTAs, 4 grid
// barriers. Fixed box [-4.8,4.8]^3, G=16 (cs=0.6, 4096 cells, ~4 pts/cell).
// R12 core change: query phase is WARP-PER-CELL — each lane owns one query
// point of the cell, the 27-cell target loop is warp-uniform (broadcast
// loads, uniform trip count, zero divergence). Single-CTA CSR scan removes
// one barrier. Uncertified queries (NN > 0.6, ~1e-4) fall back to an exact
// cooperative brute force with a finisher-ticket finalize (no extra barrier).
// Determinism: per-query mins exact; sums fixed-point u64 (order-invariant).

#define NPTS   16384
#define G      16
#define NC     (G * G * G)                 // 4096
#define NCTA   256
#define NTHR   256
#define NTOT   (NCTA * NTHR)               // 65536
#define NWARPT (NTOT / 32)                 // 2048 warps
#define NTASK  (2 * NC)                    // 8192 (cell, dir) query tasks
#define BOXB   4.8f
#define CS     (2.0f * BOXB / (float)G)    // 0.6
#define INV_CS (1.0f / CS)
#define WPQ    8                           // warps per fallback query

typedef unsigned long long u64;
typedef unsigned int u32;

// ---------- scratch (__device__ globals; zero-initialized at load) ----------
__device__ u32    g_pcnt[NC];              // packed counts c0|c1<<16 (re-zeroed)
__device__ int    g_starts[2][NC + 1];
__device__ int    g_cursor[2][NC];
__device__ float4 g_pre[2][NPTS];          // staged {-2x,-2y,-2z,|p|^2}
__device__ int    g_cellid[2][NPTS];
__device__ float4 g_sorted[2][NPTS];
__device__ int    g_fb[2 * NPTS];          // fallback: dir*NPTS + sortedIdx
__device__ u32    g_fbmin[2 * NPTS];       // fallback results (uint-float)
__device__ int    g_fb_cnt;                // reset by finisher
__device__ int    g_fb_done;               // reset by finisher
__device__ u64    g_sum;                   // reset by finisher
__device__ int    g_bar_cnt;
__device__ int    g_bar_sense;

// ---------- device-wide barrier ----------
__device__ __forceinline__ int ld_acq(const int* p) {
    int v; asm volatile("ld.acquire.gpu.b32 %0, [%1];" : "=r"(v) : "l"(p)); return v;
}
__device__ __forceinline__ void st_rel(int* p, int v) {
    asm volatile("st.release.gpu.b32 [%0], %1;" :: "l"(p), "r"(v) : "memory");
}
__device__ __forceinline__ void grid_bar(int& sense) {
    __syncthreads();
    if (threadIdx.x == 0) {
        int target = sense ^ 1;
        __threadfence();
        int a = atomicAdd(&g_bar_cnt, 1);
        if (a == NCTA - 1) {
            atomicExch(&g_bar_cnt, 0);      // reset BEFORE release
            st_rel(&g_bar_sense, target);
        } else {
            while (ld_acq(&g_bar_sense) != target) __nanosleep(32);
        }
        __threadfence();
    }
    sense ^= 1;
    __syncthreads();
}

__device__ __forceinline__ int cell1(float v) {
    int c = (int)floorf((v + BOXB) * INV_CS);
    return c < 0 ? 0 : (c > G - 1 ? G - 1 : c);
}

__device__ __forceinline__ float pdist(float4 B, float qx, float qy, float qz) {
    return fmaf(qz, B.z, fmaf(qy, B.y, fmaf(qx, B.x, B.w)));
}

__global__ __launch_bounds__(NTHR, 4)
void cd_fused_kernel(const float* __restrict__ gt, const float* __restrict__ gen,
                     float* __restrict__ out) {
    __shared__ u32 s_wsum[8];

    const int tid  = threadIdx.x;
    const int t    = blockIdx.x * NTHR + tid;       // 0 .. NTOT-1
    const int wid  = tid >> 5, lane = tid & 31;
    int sense = ld_acq(&g_bar_sense);

    // ---- P1: packed histogram + stage + fbmin reinit ----
    if (t < 2 * NPTS) {
        const int cloud = t >> 14, i = t & (NPTS - 1);
        const float* p = (cloud == 0 ? gt : gen) + 3 * i;
        float x = p[0], y = p[1], z = p[2];
        int cell = (cell1(z) * G + cell1(y)) * G + cell1(x);
        atomicAdd(&g_pcnt[cell], cloud == 0 ? 1u : 0x10000u);
        g_pre[cloud][i]    = make_float4(-2.0f * x, -2.0f * y, -2.0f * z,
                                         x * x + y * y + z * z);
        g_cellid[cloud][i] = cell;
        g_fbmin[t] = 0x7F800000u;                   // +inf
    }
    grid_bar(sense);                                // GB1

    // ---- P2: single-CTA packed scan (CTA 0: 16 cells/thread) ----
    if (blockIdx.x == 0) {
        u32 v[16];
        const uint4* src = (const uint4*)(g_pcnt + tid * 16);
#pragma unroll
        for (int k = 0; k < 4; k++) {
            uint4 q = src[k];
            v[k * 4 + 0] = q.x; v[k * 4 + 1] = q.y;
            v[k * 4 + 2] = q.z; v[k * 4 + 3] = q.w;
        }
        u32 tot = 0;
#pragma unroll
        for (int k = 0; k < 16; k++) tot += v[k];   // packed, carry-free
        u32 incl = tot;
#pragma unroll
        for (int s = 1; s < 32; s <<= 1) {
            u32 n = __shfl_up_sync(0xFFFFFFFFu, incl, s);
            if (lane >= s) incl += n;
        }
        if (lane == 31) s_wsum[wid] = incl;
        __syncthreads();
        if (wid == 0) {
            u32 w = (lane < 8) ? s_wsum[lane] : 0u;
#pragma unroll
            for (int s = 1; s < 8; s <<= 1) {
                u32 n = __shfl_up_sync(0xFFFFFFFFu, w, s);
                if (lane >= s) w += n;
            }
            if (lane < 8) s_wsum[lane] = w;
        }
        __syncthreads();
        u32 run = ((wid > 0) ? s_wsum[wid - 1] : 0u) + incl - tot;
        const int base = tid * 16;
#pragma unroll
        for (int k = 0; k < 16; k++) {
            int s0 = (int)(run & 0xFFFFu), s1 = (int)(run >> 16);
            g_starts[0][base + k] = s0;  g_cursor[0][base + k] = s0;
            g_starts[1][base + k] = s1;  g_cursor[1][base + k] = s1;
            g_pcnt[base + k] = 0u;                  // re-zero for next replay
            run += v[k];
        }
        if (tid == NTHR - 1) { g_starts[0][NC] = NPTS; g_starts[1][NC] = NPTS; }
    }
    grid_bar(sense);                                // GB2

    // ---- P3: scatter into cell-sorted order ----
    if (t < 2 * NPTS) {
        const int cloud = t >> 14, i = t & (NPTS - 1);
        int cell = g_cellid[cloud][i];
        int pos  = atomicAdd(&g_cursor[cloud][cell], 1);
        g_sorted[cloud][pos] = g_pre[cloud][i];
    }
    grid_bar(sense);                                // GB3

    // ---- P4a: warp-per-(cell,dir) queries; warp-uniform target loop ----
    u64 acc = 0ull;
    {
        const int gwarp = t >> 5;
        for (int task = gwarp; task < NTASK; task += NWARPT) {
            const int dir = task >> 12;             // NC = 4096 = 2^12
            const int c   = task & (NC - 1);
            const int*    __restrict__ stq = g_starts[dir];
            const int qs = stq[c], qe = stq[c + 1];
            if (qs == qe) continue;                 // empty cell, warp-uniform

            const int cx = c & (G - 1), cy = (c >> 4) & (G - 1), cz = c >> 8;
            const float4* __restrict__ tgt = g_sorted[dir ^ 1];
            const int*    __restrict__ st  = g_starts[dir ^ 1];

            // gather <=9 warp-uniform x-row ranges (broadcast loads)
            int js[9], es[9], nr = 0;
            const int x0 = max(cx - 1, 0), x1 = min(cx + 1, G - 1);
#pragma unroll
            for (int dz = -1; dz <= 1; dz++) {
                int z = cz + dz;
                if ((unsigned)z >= G) continue;
#pragma unroll
                for (int dy = -1; dy <= 1; dy++) {
                    int y = cy + dy;
                    if ((unsigned)y >= G) continue;
                    int rb = (z * G + y) * G;
                    js[nr] = __ldg(&st[rb + x0]);
                    es[nr] = __ldg(&st[rb + x1 + 1]);
                    nr++;
                }
            }

            for (int qb = qs; qb < qe; qb += 32) {  // usually one block
                const int myq   = qb + lane;
                const bool act  = myq < qe;
                const int qidx  = act ? myq : qs;
                float4 A = __ldg(&g_sorted[dir][qidx]);
                float qx = -0.5f * A.x, qy = -0.5f * A.y, qz = -0.5f * A.z;
                float an = A.w;
                float m = 3.4e38f;

                for (int r = 0; r < nr; r++) {      // warp-uniform
                    int j = js[r], e = es[r];
                    for (; j + 1 < e; j += 2) {     // 2-deep ILP, broadcast
                        float4 B0 = __ldg(&tgt[j]);
                        float4 B1 = __ldg(&tgt[j + 1]);
                        m = fminf(m, pdist(B0, qx, qy, qz));
                        m = fminf(m, pdist(B1, qx, qy, qz));
                    }
                    if (j < e)
                        m = fminf(m, pdist(__ldg(&tgt[j]), qx, qy, qz));
                }

                if (act) {
                    float d = fmaxf(m + an, 0.0f);
                    if (d <= CS * CS) {             // certified at r=1
                        acc += (u64)((double)d * 4294967296.0);
                    } else {                        // enqueue exact fallback
                        int slot = atomicAdd(&g_fb_cnt, 1);
                        g_fb[slot] = dir * NPTS + myq;
                    }
                }
            }
        }
    }
    __syncwarp();
#pragma unroll
    for (int s = 16; s > 0; s >>= 1)
        acc += __shfl_down_sync(0xFFFFFFFFu, acc, s);
    if (lane == 0 && acc) atomicAdd(&g_sum, acc);
    grid_bar(sense);                                // GB4 (last barrier)

    // ---- P4b: cooperative brute force; LAST job's warp finalizes ----
    const int nf = *((volatile int*)&g_fb_cnt);
    const int njobs = nf * WPQ;
    if (njobs > 0) {
        const int gwarp = t >> 5;
        for (int job = gwarp; job < njobs; job += NWARPT) {
            int f = job >> 3, slice = job & (WPQ - 1);
            int qi = g_fb[f];
            int dir = qi >> 14, i = qi & (NPTS - 1);
            float4 A = __ldg(&g_sorted[dir][i]);
            float qx = -0.5f * A.x, qy = -0.5f * A.y, qz = -0.5f * A.z;
            float an = A.w;
            const float4* __restrict__ tgt = g_sorted[dir ^ 1];
            float m = 3.4e38f;
            int base = slice * (NPTS / WPQ) + lane;
#pragma unroll 8
            for (int j = 0; j < NPTS / WPQ / 32; j++) {   // 64 coalesced loads
                float4 B = __ldg(&tgt[base + j * 32]);
                m = fminf(m, pdist(B, qx, qy, qz));
            }
#pragma unroll
            for (int s = 16; s > 0; s >>= 1)
                m = fminf(m, __shfl_xor_sync(0xFFFFFFFFu, m, s));
            int ticket = 0;
            if (lane == 0) {
                atomicMin(&g_fbmin[f], __float_as_uint(fmaxf(m + an, 0.0f)));
                __threadfence();
                ticket = atomicAdd(&g_fb_done, 1) + 1;
            }
            ticket = __shfl_sync(0xFFFFFFFFu, ticket, 0);
            if (ticket == njobs) {                  // this warp finished last
                __threadfence();
                u64 a2 = 0ull;
                for (int f2 = lane; f2 < nf; f2 += 32)
                    a2 += (u64)((double)__uint_as_float(
                              *((volatile u32*)&g_fbmin[f2])) * 4294967296.0);
#pragma unroll
                for (int s = 16; s > 0; s >>= 1)
                    a2 += __shfl_down_sync(0xFFFFFFFFu, a2, s);
                if (lane == 0) {
                    u64 tot = atomicAdd(&g_sum, a2) + a2;
                    double sd = (double)tot * (1.0 / 4294967296.0);
                    out[0] = (float)(sd / (double)NPTS);  // mean1 + mean2
                    g_sum = 0ull; g_fb_cnt = 0; g_fb_done = 0;
                    __threadfence();
                }
            }
        }
    } else if (t == 0) {                            // no fallback: finalize now
        u64 tot = atomicAdd(&g_sum, 0ull);
        double sd = (double)tot * (1.0 / 4294967296.0);
        out[0] = (float)(sd / (double)NPTS);
        g_sum = 0ull; g_fb_cnt = 0; g_fb_done = 0;
        __threadfence();
    }
}

extern "C" void kernel_launch(void* const* d_in, const int* in_sizes, int n_in,
                              void* d_out, int out_size) {
    const float* gt  = (const float*)d_in[0];
    const float* gen = (const float*)d_in[1];
    float* out = (float*)d_out;
    cd_fused_kernel<<<NCTA, NTHR>>>(gt, gen, out);
}

// round 13
// speedup vs baseline: 3.0670x; 3.0670x over previous
#include <cuda_runtime.h>
#include <cstdint>

// Chamfer distance via uniform grid, G=16 (cs=0.6, ~4 pts/cell), as FIVE
// stream-ordered kernels (no persistent kernel, no spin barriers — R12's
// persistent variant ran 4.4us profiled but 4477us in the timed harness).
// K1 hist+stage  K2 single-CTA CSR scan (re-zeros counts for next replay)
// K3 scatter     K4 warp-per-(cell,dir) query: warp-uniform 27-cell loop
// K5 fallback brute force (exact) + ticket finalize (resets accumulators).
// Determinism: per-query mins exact; totals fixed-point u64 (order-invariant).

#define NPTS   16384
#define G      16
#define NC     (G * G * G)                 // 4096
#define BOXB   4.8f
#define CS     (2.0f * BOXB / (float)G)    // 0.6
#define INV_CS (1.0f / CS)
#define WPQ    8                           // warps per fallback query

typedef unsigned long long u64;
typedef unsigned int u32;

// ---------- scratch (__device__ globals; zero-initialized at load) ----------
__device__ __align__(16) u32 g_pcnt[NC];   // packed counts c0|c1<<16 (re-zeroed by K2)
__device__ int    g_starts[2][NC + 1];
__device__ int    g_cursor[2][NC];
__device__ float4 g_pre[2][NPTS];          // staged {-2x,-2y,-2z,|p|^2}
__device__ int    g_cellid[2][NPTS];
__device__ float4 g_sorted[2][NPTS];
__device__ int    g_fb[2 * NPTS];          // fallback: dir*NPTS + sortedIdx
__device__ u32    g_fbmin[2 * NPTS];       // fallback results (uint-float)
__device__ int    g_fb_cnt;                // reset by K5 finisher
__device__ int    g_fb_done;               // reset by K5 finisher
__device__ u64    g_sum;                   // reset by K5 finisher

__device__ __forceinline__ int cell1(float v) {
    int c = (int)floorf((v + BOXB) * INV_CS);
    return c < 0 ? 0 : (c > G - 1 ? G - 1 : c);
}
__device__ __forceinline__ float pdist(float4 B, float qx, float qy, float qz) {
    return fmaf(qz, B.z, fmaf(qy, B.y, fmaf(qx, B.x, B.w)));
}

// ---------- K1: packed histogram + stage + fbmin reinit ----------
__global__ __launch_bounds__(256)
void k1_hist(const float* __restrict__ gt, const float* __restrict__ gen) {
    const int t = blockIdx.x * 256 + threadIdx.x;   // 0 .. 2*NPTS-1
    const int cloud = t >> 14, i = t & (NPTS - 1);
    const float* p = (cloud == 0 ? gt : gen) + 3 * i;
    float x = p[0], y = p[1], z = p[2];
    int cell = (cell1(z) * G + cell1(y)) * G + cell1(x);
    atomicAdd(&g_pcnt[cell], cloud == 0 ? 1u : 0x10000u);
    g_pre[cloud][i]    = make_float4(-2.0f * x, -2.0f * y, -2.0f * z,
                                     x * x + y * y + z * z);
    g_cellid[cloud][i] = cell;
    g_fbmin[t] = 0x7F800000u;                       // +inf
}

// ---------- K2: single-CTA packed scan; re-zero counts for next replay ----------
__global__ __launch_bounds__(256)
void k2_scan() {
    __shared__ u32 s_wsum[8];
    const int tid = threadIdx.x, wid = tid >> 5, lane = tid & 31;

    u32 v[16];
    const uint4* src = (const uint4*)(g_pcnt + tid * 16);
#pragma unroll
    for (int k = 0; k < 4; k++) {
        uint4 q = src[k];
        v[k * 4 + 0] = q.x; v[k * 4 + 1] = q.y;
        v[k * 4 + 2] = q.z; v[k * 4 + 3] = q.w;
    }
    u32 tot = 0;
#pragma unroll
    for (int k = 0; k < 16; k++) tot += v[k];       // packed, carry-free
    u32 incl = tot;
#pragma unroll
    for (int s = 1; s < 32; s <<= 1) {
        u32 n = __shfl_up_sync(0xFFFFFFFFu, incl, s);
        if (lane >= s) incl += n;
    }
    if (lane == 31) s_wsum[wid] = incl;
    __syncthreads();
    if (wid == 0) {
        u32 w = (lane < 8) ? s_wsum[lane] : 0u;
#pragma unroll
        for (int s = 1; s < 8; s <<= 1) {
            u32 n = __shfl_up_sync(0xFFFFFFFFu, w, s);
            if (lane >= s) w += n;
        }
        if (lane < 8) s_wsum[lane] = w;
    }
    __syncthreads();
    u32 run = ((wid > 0) ? s_wsum[wid - 1] : 0u) + incl - tot;
    const int base = tid * 16;
#pragma unroll
    for (int k = 0; k < 16; k++) {
        int s0 = (int)(run & 0xFFFFu), s1 = (int)(run >> 16);
        g_starts[0][base + k] = s0;  g_cursor[0][base + k] = s0;
        g_starts[1][base + k] = s1;  g_cursor[1][base + k] = s1;
        g_pcnt[base + k] = 0u;                      // ready for next replay
        run += v[k];
    }
    if (tid == 255) { g_starts[0][NC] = NPTS; g_starts[1][NC] = NPTS; }
}

// ---------- K3: scatter into cell-sorted order ----------
__global__ __launch_bounds__(256)
void k3_scatter() {
    const int t = blockIdx.x * 256 + threadIdx.x;
    const int cloud = t >> 14, i = t & (NPTS - 1);
    int cell = g_cellid[cloud][i];
    int pos  = atomicAdd(&g_cursor[cloud][cell], 1);
    g_sorted[cloud][pos] = g_pre[cloud][i];
}

// ---------- K4: warp-per-(cell,dir) query; warp-uniform target loop ----------
#define K4_CTAS  256
#define K4_WARPS (K4_CTAS * 8)             // 2048 warps, 4 tasks each
__global__ __launch_bounds__(256)
void k4_query() {
    const int tid = threadIdx.x, lane = tid & 31;
    const int gwarp = (blockIdx.x * 256 + tid) >> 5;
    u64 acc = 0ull;

    for (int task = gwarp; task < 2 * NC; task += K4_WARPS) {
        const int dir = task >> 12;                 // NC = 4096 = 2^12
        const int c   = task & (NC - 1);
        const int* __restrict__ stq = g_starts[dir];
        const int qs = stq[c], qe = stq[c + 1];
        if (qs == qe) continue;                     // warp-uniform skip

        const int cx = c & (G - 1), cy = (c >> 4) & (G - 1), cz = c >> 8;
        const float4* __restrict__ tgt = g_sorted[dir ^ 1];
        const int*    __restrict__ st  = g_starts[dir ^ 1];

        int js[9], es[9], nr = 0;                   // warp-uniform row ranges
        const int x0 = max(cx - 1, 0), x1 = min(cx + 1, G - 1);
#pragma unroll
        for (int dz = -1; dz <= 1; dz++) {
            int z = cz + dz;
            if ((unsigned)z >= G) continue;
#pragma unroll
            for (int dy = -1; dy <= 1; dy++) {
                int y = cy + dy;
                if ((unsigned)y >= G) continue;
                int rb = (z * G + y) * G;
                js[nr] = __ldg(&st[rb + x0]);
                es[nr] = __ldg(&st[rb + x1 + 1]);
                nr++;
            }
        }

        for (int qb = qs; qb < qe; qb += 32) {      // usually one block
            const int myq  = qb + lane;
            const bool act = myq < qe;
            float4 A = __ldg(&g_sorted[dir][act ? myq : qs]);
            float qx = -0.5f * A.x, qy = -0.5f * A.y, qz = -0.5f * A.z;
            float an = A.w;
            float m = 3.4e38f;

            for (int r = 0; r < nr; r++) {          // warp-uniform trip counts
                int j = js[r], e = es[r];
                for (; j + 1 < e; j += 2) {         // broadcast loads, 2-deep
                    float4 B0 = __ldg(&tgt[j]);
                    float4 B1 = __ldg(&tgt[j + 1]);
                    m = fminf(m, pdist(B0, qx, qy, qz));
                    m = fminf(m, pdist(B1, qx, qy, qz));
                }
                if (j < e) m = fminf(m, pdist(__ldg(&tgt[j]), qx, qy, qz));
            }

            if (act) {
                float d = fmaxf(m + an, 0.0f);
                if (d <= CS * CS) {                 // certified at r=1
                    acc += (u64)((double)d * 4294967296.0);
                } else {                            // rare: exact fallback
                    int slot = atomicAdd(&g_fb_cnt, 1);
                    g_fb[slot] = dir * NPTS + myq;
                }
            }
        }
    }
    __syncwarp();
#pragma unroll
    for (int s = 16; s > 0; s >>= 1)
        acc += __shfl_down_sync(0xFFFFFFFFu, acc, s);
    if (lane == 0 && acc) atomicAdd(&g_sum, acc);
}

// ---------- K5: fallback brute force + ticket finalize ----------
#define K5_CTAS  128
#define K5_WARPS (K5_CTAS * 8)             // 1024 warps
__global__ __launch_bounds__(256)
void k5_finish(float* __restrict__ out) {
    const int tid = threadIdx.x, lane = tid & 31;
    const int gwarp = (blockIdx.x * 256 + tid) >> 5;
    const int nf = *((volatile int*)&g_fb_cnt);
    const int njobs = nf * WPQ;

    if (njobs == 0) {
        if (blockIdx.x == 0 && tid == 0) {
            u64 tot = atomicAdd(&g_sum, 0ull);
            double sd = (double)tot * (1.0 / 4294967296.0);
            out[0] = (float)(sd / (double)NPTS);    // mean1 + mean2
            g_sum = 0ull; g_fb_cnt = 0; g_fb_done = 0;
            __threadfence();
        }
        return;
    }

    for (int job = gwarp; job < njobs; job += K5_WARPS) {
        int f = job >> 3, slice = job & (WPQ - 1);
        int qi = g_fb[f];
        int dir = qi >> 14, i = qi & (NPTS - 1);
        float4 A = __ldg(&g_sorted[dir][i]);
        float qx = -0.5f * A.x, qy = -0.5f * A.y, qz = -0.5f * A.z;
        float an = A.w;
        const float4* __restrict__ tgt = g_sorted[dir ^ 1];
        float m = 3.4e38f;
        int base = slice * (NPTS / WPQ) + lane;
#pragma unroll 8
        for (int j = 0; j < NPTS / WPQ / 32; j++) { // 64 coalesced loads
            float4 B = __ldg(&tgt[base + j * 32]);
            m = fminf(m, pdist(B, qx, qy, qz));
        }
#pragma unroll
        for (int s = 16; s > 0; s >>= 1)
            m = fminf(m, __shfl_xor_sync(0xFFFFFFFFu, m, s));
        int ticket = 0;
        if (lane == 0) {
            atomicMin(&g_fbmin[f], __float_as_uint(fmaxf(m + an, 0.0f)));
            __threadfence();
            ticket = atomicAdd(&g_fb_done, 1) + 1;
        }
        ticket = __shfl_sync(0xFFFFFFFFu, ticket, 0);
        if (ticket == njobs) {                      // last-completing job
            __threadfence();
            u64 a2 = 0ull;
            for (int f2 = lane; f2 < nf; f2 += 32)
                a2 += (u64)((double)__uint_as_float(
                          *((volatile u32*)&g_fbmin[f2])) * 4294967296.0);
#pragma unroll
            for (int s = 16; s > 0; s >>= 1)
                a2 += __shfl_down_sync(0xFFFFFFFFu, a2, s);
            if (lane == 0) {
                u64 tot = atomicAdd(&g_sum, a2) + a2;
                double sd = (double)tot * (1.0 / 4294967296.0);
                out[0] = (float)(sd / (double)NPTS);
                g_sum = 0ull; g_fb_cnt = 0; g_fb_done = 0;
                __threadfence();
            }
        }
    }
}

extern "C" void kernel_launch(void* const* d_in, const int* in_sizes, int n_in,
                              void* d_out, int out_size) {
    const float* gt  = (const float*)d_in[0];
    const float* gen = (const float*)d_in[1];
    float* out = (float*)d_out;

    k1_hist   <<<(2 * NPTS) / 256, 256>>>(gt, gen);
    k2_scan   <<<1, 256>>>();
    k3_scatter<<<(2 * NPTS) / 256, 256>>>();
    k4_query  <<<K4_CTAS, 256>>>();
    k5_finish <<<K5_CTAS, 256>>>(out);
}

// round 15
// speedup vs baseline: 11.5086x; 3.7524x over previous
#include <cuda_runtime.h>
#include <cstdint>

// Chamfer distance: ONE persistent kernel in the R11 structural template
// (512 co-resident CTAs, 5 sense-reversing grid barriers — the regime that
// benches faithfully), with the query phase replaced by WARP-PER-(CELL,DIR)
// tasks at G=24 (cs=0.4): the 27-cell target loop is warp-uniform (broadcast
// loads, uniform trip counts, no divergence). No r=2 escalation: queries not
// certified by the r=1 bound (NN > 0.4, ~150 of 32768) go to the exact
// cooperative brute-force fallback with finisher-ticket finalize.
// Determinism: per-query mins exact; totals fixed-point u64 (order-invariant).

#define NPTS   16384
#define G      24
#define NC     (G * G * G)                 // 13824
#define NCTA   512
#define NTHR   256
#define NTOT   (NCTA * NTHR)               // 131072
#define NWARPT (NTOT / 32)                 // 4096 warps
#define BOXB   4.8f
#define CS     (2.0f * BOXB / (float)G)    // 0.4
#define INV_CS (1.0f / CS)                 // 2.5
#define CS2    (CS * CS)                   // 0.16 certification bound
#define WPQ    8                           // warps per fallback query

typedef unsigned long long u64;
typedef unsigned int u32;

// ---------- scratch (__device__ globals; zero-initialized at load) ----------
__device__ u32    g_pcnt[NC];              // packed counts c0|c1<<16 (re-zeroed)
__device__ int    g_starts[2][NC + 1];
__device__ int    g_cursor[2][NC];
__device__ u32    g_part[NCTA];            // packed CTA partial sums
__device__ float4 g_pre[2][NPTS];          // staged {-2x,-2y,-2z,|p|^2}
__device__ int    g_cellid[2][NPTS];
__device__ float4 g_sorted[2][NPTS];
__device__ int    g_fb[2 * NPTS];          // fallback: dir*NPTS + sortedIdx
__device__ u32    g_fbmin[2 * NPTS];       // fallback results (uint-float)
__device__ int    g_fb_cnt;                // reset by finisher
__device__ int    g_fb_done;               // reset by finisher
__device__ u64    g_sum;                   // reset by finisher
__device__ int    g_bar_cnt;
__device__ int    g_bar_sense;

// ---------- device-wide barrier (unchanged from R11) ----------
__device__ __forceinline__ int ld_acq(const int* p) {
    int v; asm volatile("ld.acquire.gpu.b32 %0, [%1];" : "=r"(v) : "l"(p)); return v;
}
__device__ __forceinline__ void st_rel(int* p, int v) {
    asm volatile("st.release.gpu.b32 [%0], %1;" :: "l"(p), "r"(v) : "memory");
}
__device__ __forceinline__ void grid_bar(int& sense) {
    __syncthreads();
    if (threadIdx.x == 0) {
        int target = sense ^ 1;
        __threadfence();
        int a = atomicAdd(&g_bar_cnt, 1);
        if (a == NCTA - 1) {
            atomicExch(&g_bar_cnt, 0);      // reset BEFORE release
            st_rel(&g_bar_sense, target);
        } else {
            while (ld_acq(&g_bar_sense) != target) __nanosleep(32);
        }
        __threadfence();
    }
    sense ^= 1;
    __syncthreads();
}

__device__ __forceinline__ int cell1(float v) {
    int c = (int)floorf((v + BOXB) * INV_CS);
    return c < 0 ? 0 : (c > G - 1 ? G - 1 : c);
}
__device__ __forceinline__ float pdist(float4 B, float qx, float qy, float qz) {
    return fmaf(qz, B.z, fmaf(qy, B.y, fmaf(qx, B.x, B.w)));
}

__global__ __launch_bounds__(NTHR, 4)
void cd_fused_kernel(const float* __restrict__ gt, const float* __restrict__ gen,
                     float* __restrict__ out) {
    __shared__ u32 s_wsum[8];
    __shared__ u32 s_off;

    const int tid  = threadIdx.x;
    const int t    = blockIdx.x * NTHR + tid;       // 0 .. NTOT-1
    const int wid  = tid >> 5, lane = tid & 31;
    int sense = ld_acq(&g_bar_sense);

    // ---- P1: packed histogram + stage + fbmin reinit ----
    if (t < 2 * NPTS) {
        const int cloud = t >> 14, i = t & (NPTS - 1);
        const float* p = (cloud == 0 ? gt : gen) + 3 * i;
        float x = p[0], y = p[1], z = p[2];
        int cell = (cell1(z) * G + cell1(y)) * G + cell1(x);
        atomicAdd(&g_pcnt[cell], cloud == 0 ? 1u : 0x10000u);
        g_pre[cloud][i]    = make_float4(-2.0f * x, -2.0f * y, -2.0f * z,
                                         x * x + y * y + z * z);
        g_cellid[cloud][i] = cell;
        g_fbmin[t] = 0x7F800000u;                   // +inf
    }
    grid_bar(sense);                                // GB1

    // ---- P2a: packed two-level warp scan, one cell per thread ----
    const int  cidx = t;
    const bool cact = (cidx < NC);
    const u32  cnt  = cact ? g_pcnt[cidx] : 0u;     // carry-free packed halves
    u32 incl = cnt;
#pragma unroll
    for (int s = 1; s < 32; s <<= 1) {
        u32 n = __shfl_up_sync(0xFFFFFFFFu, incl, s);
        if (lane >= s) incl += n;
    }
    if (lane == 31) s_wsum[wid] = incl;
    __syncthreads();
    if (wid == 0) {
        u32 w = (lane < 8) ? s_wsum[lane] : 0u;
#pragma unroll
        for (int s = 1; s < 8; s <<= 1) {
            u32 n = __shfl_up_sync(0xFFFFFFFFu, w, s);
            if (lane >= s) w += n;
        }
        if (lane < 8) s_wsum[lane] = w;
    }
    __syncthreads();
    const u32 wbase = (wid > 0) ? s_wsum[wid - 1] : 0u;
    const u32 excl  = wbase + incl - cnt;           // packed exclusive prefix
    if (tid == NTHR - 1) g_part[blockIdx.x] = wbase + incl;  // packed CTA total
    grid_bar(sense);                                // GB2

    // ---- P2b: packed global offset, publish CSR, re-zero counts ----
    if (wid == 0) {
        u32 acc0 = 0u;
#pragma unroll
        for (int k = 0; k < NCTA / 32; k++) {
            int idx = k * 32 + lane;
            u32 pv = g_part[idx];
            if (idx < blockIdx.x) acc0 += pv;
        }
#pragma unroll
        for (int s = 16; s > 0; s >>= 1)
            acc0 += __shfl_xor_sync(0xFFFFFFFFu, acc0, s);
        if (lane == 0) s_off = acc0;
    }
    __syncthreads();
    if (cact) {
        u32 pk = s_off + excl;                      // packed starts
        int s0 = (int)(pk & 0xFFFFu), s1 = (int)(pk >> 16);
        g_starts[0][cidx] = s0;  g_cursor[0][cidx] = s0;
        g_starts[1][cidx] = s1;  g_cursor[1][cidx] = s1;
        g_pcnt[cidx] = 0u;                          // re-zero for next replay
    }
    if (t == 0) { g_starts[0][NC] = NPTS; g_starts[1][NC] = NPTS; }
    grid_bar(sense);                                // GB3

    // ---- P3: scatter into cell-sorted order ----
    if (t < 2 * NPTS) {
        const int cloud = t >> 14, i = t & (NPTS - 1);
        int cell = g_cellid[cloud][i];
        int pos  = atomicAdd(&g_cursor[cloud][cell], 1);
        g_sorted[cloud][pos] = g_pre[cloud][i];
    }
    grid_bar(sense);                                // GB4

    // ---- P4a: warp-per-(cell,dir) queries; warp-uniform 27-cell loop ----
    u64 acc = 0ull;
    {
        const int gwarp = t >> 5;
        for (int task = gwarp; task < 2 * NC; task += NWARPT) {
            int dir = 0, c = task;
            if (c >= NC) { dir = 1; c -= NC; }
            const int* __restrict__ stq = g_starts[dir];
            const int qs = stq[c], qe = stq[c + 1];
            if (qs == qe) continue;                 // warp-uniform skip

            const int cx = c % G, cy = (c / G) % G, cz = c / (G * G);
            const float4* __restrict__ tgt = g_sorted[dir ^ 1];
            const int*    __restrict__ st  = g_starts[dir ^ 1];

            int js[9], es[9], nr = 0;               // warp-uniform row ranges
            const int x0 = max(cx - 1, 0), x1 = min(cx + 1, G - 1);
#pragma unroll
            for (int dz = -1; dz <= 1; dz++) {
                int z = cz + dz;
                if ((unsigned)z >= G) continue;
#pragma unroll
                for (int dy = -1; dy <= 1; dy++) {
                    int y = cy + dy;
                    if ((unsigned)y >= G) continue;
                    int rb = (z * G + y) * G;
                    js[nr] = __ldg(&st[rb + x0]);
                    es[nr] = __ldg(&st[rb + x1 + 1]);
                    nr++;
                }
            }

            for (int qb = qs; qb < qe; qb += 32) {  // almost always 1 pass
                const int myq  = qb + lane;
                const bool act = myq < qe;
                float4 A = __ldg(&g_sorted[dir][act ? myq : qs]);
                float qx = -0.5f * A.x, qy = -0.5f * A.y, qz = -0.5f * A.z;
                float an = A.w;
                float m = 3.4e38f;

                for (int r = 0; r < nr; r++) {      // warp-uniform trip counts
                    int j = js[r], e = es[r];
                    for (; j + 1 < e; j += 2) {     // broadcast loads, 2-deep
                        float4 B0 = __ldg(&tgt[j]);
                        float4 B1 = __ldg(&tgt[j + 1]);
                        m = fminf(m, pdist(B0, qx, qy, qz));
                        m = fminf(m, pdist(B1, qx, qy, qz));
                    }
                    if (j < e) m = fminf(m, pdist(__ldg(&tgt[j]), qx, qy, qz));
                }

                if (act) {
                    float d = fmaxf(m + an, 0.0f);
                    if (d <= CS2) {                 // certified at r=1
                        acc += (u64)((double)d * 4294967296.0);
                    } else {                        // rare: exact fallback
                        int slot = atomicAdd(&g_fb_cnt, 1);
                        g_fb[slot] = dir * NPTS + myq;
                    }
                }
            }
        }
    }
    __syncwarp();
#pragma unroll
    for (int s = 16; s > 0; s >>= 1)
        acc += __shfl_down_sync(0xFFFFFFFFu, acc, s);
    if (lane == 0 && acc) atomicAdd(&g_sum, acc);
    grid_bar(sense);                                // GB5 (last barrier)

    // ---- P4b: cooperative brute force; LAST job's warp finalizes ----
    const int nf = *((volatile int*)&g_fb_cnt);
    const int njobs = nf * WPQ;
    if (njobs > 0) {
        const int gwarp = t >> 5;
        for (int job = gwarp; job < njobs; job += NWARPT) {
            int f = job >> 3, slice = job & (WPQ - 1);
            int qi = g_fb[f];
            int dir = qi >> 14, i = qi & (NPTS - 1);
            float4 A = __ldg(&g_sorted[dir][i]);
            float qx = -0.5f * A.x, qy = -0.5f * A.y, qz = -0.5f * A.z;
            float an = A.w;
            const float4* __restrict__ tgt = g_sorted[dir ^ 1];
            float m = 3.4e38f;
            int base = slice * (NPTS / WPQ) + lane;
#pragma unroll 8
            for (int j = 0; j < NPTS / WPQ / 32; j++) {   // 64 coalesced loads
                float4 B = __ldg(&tgt[base + j * 32]);
                m = fminf(m, pdist(B, qx, qy, qz));
            }
#pragma unroll
            for (int s = 16; s > 0; s >>= 1)
                m = fminf(m, __shfl_xor_sync(0xFFFFFFFFu, m, s));
            int ticket = 0;
            if (lane == 0) {
                atomicMin(&g_fbmin[f], __float_as_uint(fmaxf(m + an, 0.0f)));
                __threadfence();
                ticket = atomicAdd(&g_fb_done, 1) + 1;
            }
            ticket = __shfl_sync(0xFFFFFFFFu, ticket, 0);
            if (ticket == njobs) {                  // this warp finished last
                __threadfence();
                u64 a2 = 0ull;
                for (int f2 = lane; f2 < nf; f2 += 32)
                    a2 += (u64)((double)__uint_as_float(
                              *((volatile u32*)&g_fbmin[f2])) * 4294967296.0);
#pragma unroll
                for (int s = 16; s > 0; s >>= 1)
                    a2 += __shfl_down_sync(0xFFFFFFFFu, a2, s);
                if (lane == 0) {
                    u64 tot = atomicAdd(&g_sum, a2) + a2;
                    double sd = (double)tot * (1.0 / 4294967296.0);
                    out[0] = (float)(sd / (double)NPTS);  // mean1 + mean2
                    g_sum = 0ull; g_fb_cnt = 0; g_fb_done = 0;
                    __threadfence();
                }
            }
        }
    } else if (t == 0) {                            // no fallback: finalize now
        u64 tot = atomicAdd(&g_sum, 0ull);
        double sd = (double)tot * (1.0 / 4294967296.0);
        out[0] = (float)(sd / (double)NPTS);
        g_sum = 0ull; g_fb_cnt = 0; g_fb_done = 0;
        __threadfence();
    }
}

extern "C" void kernel_launch(void* const* d_in, const int* in_sizes, int n_in,
                              void* d_out, int out_size) {
    const float* gt  = (const float*)d_in[0];
    const float* gen = (const float*)d_in[1];
    float* out = (float*)d_out;
    cd_fused_kernel<<<NCTA, NTHR>>>(gt, gen, out);
}

// round 16
// speedup vs baseline: 90.2211x; 7.8395x over previous
#include <cuda_runtime.h>
#include <cstdint>

// Chamfer distance: ONE persistent kernel, 512 co-resident CTAs, 131072
// threads = 4 lanes per (cloud,point) query. Fixed box [-4.8,4.8]^3.
// R15 = R11 verbatim with ONE change: G 48 -> 32 (cs 0.2 -> 0.3).
// Rationale: at G=48 the r=2 escalation fired for ~15% of queries (73% of
// warps paid the 25-row scan); at G=32 escalation needs NN^2 > 0.09 (~2-3%)
// and the r<=2 certification bound rises to 0.36, shrinking the exact
// brute-force fallback to ~100 queries.
// Determinism: per-query mins exact; sums fixed-point u64 (order-invariant).

#define NPTS   16384
#define G      32
#define NC     (G * G * G)                 // 32768
#define NCTA   512
#define NTHR   256
#define NTOT   (NCTA * NTHR)               // 131072 = 4 * 2 * NPTS
#define NWARP  (NTOT / 32)                 // 4096
#define BOXB   4.8f
#define CS     (2.0f * BOXB / (float)G)    // 0.3
#define INV_CS (1.0f / CS)
#define WPQ    8                           // warps per fallback query

typedef unsigned long long u64;
typedef unsigned int u32;

// ---------- scratch (__device__ globals; zero-initialized at load) ----------
__device__ u32    g_pcnt[NC];              // packed counts: c0 | c1<<16 (re-zeroed)
__device__ int    g_starts[2][NC + 1];
__device__ int    g_cursor[2][NC];
__device__ u32    g_part[NCTA];            // packed CTA partial sums
__device__ float4 g_pre[2][NPTS];          // staged {-2x,-2y,-2z,|p|^2}
__device__ int    g_cellid[2][NPTS];
__device__ float4 g_sorted[2][NPTS];
__device__ int    g_fb[2 * NPTS];          // fallback query ids
__device__ u32    g_fbmin[2 * NPTS];       // fallback results (uint-float)
__device__ int    g_fb_cnt;                // reset by finisher
__device__ int    g_fb_done;               // finisher ticket; reset by finisher
__device__ u64    g_sum;                   // reset by finisher
__device__ int    g_bar_cnt;
__device__ int    g_bar_sense;

// ---------- device-wide barrier ----------
__device__ __forceinline__ int ld_acq(const int* p) {
    int v; asm volatile("ld.acquire.gpu.b32 %0, [%1];" : "=r"(v) : "l"(p)); return v;
}
__device__ __forceinline__ void st_rel(int* p, int v) {
    asm volatile("st.release.gpu.b32 [%0], %1;" :: "l"(p), "r"(v) : "memory");
}
__device__ __forceinline__ void grid_bar(int& sense) {
    __syncthreads();
    if (threadIdx.x == 0) {
        int target = sense ^ 1;
        __threadfence();
        int a = atomicAdd(&g_bar_cnt, 1);
        if (a == NCTA - 1) {
            atomicExch(&g_bar_cnt, 0);      // reset BEFORE release
            st_rel(&g_bar_sense, target);
        } else {
            while (ld_acq(&g_bar_sense) != target) __nanosleep(32);
        }
        __threadfence();
    }
    sense ^= 1;
    __syncthreads();
}

__device__ __forceinline__ int cell1(float v) {
    int c = (int)floorf((v + BOXB) * INV_CS);
    return c < 0 ? 0 : (c > G - 1 ? G - 1 : c);
}

__device__ __forceinline__ float pdist(float4 B, float qx, float qy, float qz) {
    return fmaf(qz, B.z, fmaf(qy, B.y, fmaf(qx, B.x, B.w)));
}

__device__ __forceinline__ void scan_range(const float4* __restrict__ tgt,
                                           int j, int e,
                                           float qx, float qy, float qz, float& m) {
    for (; j < e; j++) m = fminf(m, pdist(__ldg(&tgt[j]), qx, qy, qz));
}

__global__ __launch_bounds__(NTHR, 4)
void cd_fused_kernel(const float* __restrict__ gt, const float* __restrict__ gen,
                     float* __restrict__ out) {
    __shared__ u32 s_wsum[8];              // per-warp packed totals
    __shared__ u32 s_off;                  // packed global CTA offset

    const int tid  = threadIdx.x;
    const int t    = blockIdx.x * NTHR + tid;       // 0 .. NTOT-1
    const int wid  = tid >> 5, lane = tid & 31;
    int sense = ld_acq(&g_bar_sense);

    // ---- P1: packed histogram + stage + fbmin reinit ----
    if (t < 2 * NPTS) {
        const int cloud = t >> 14, i = t & (NPTS - 1);
        const float* p = (cloud == 0 ? gt : gen) + 3 * i;
        float x = p[0], y = p[1], z = p[2];
        int cell = (cell1(z) * G + cell1(y)) * G + cell1(x);
        atomicAdd(&g_pcnt[cell], cloud == 0 ? 1u : 0x10000u);
        g_pre[cloud][i]    = make_float4(-2.0f * x, -2.0f * y, -2.0f * z,
                                         x * x + y * y + z * z);
        g_cellid[cloud][i] = cell;
        g_fbmin[t] = 0x7F800000u;                   // +inf
    }
    grid_bar(sense);                                // GB1

    // ---- P2a: packed two-level warp scan, one cell per thread ----
    const int  cidx = t;
    const bool cact = (cidx < NC);
    const u32  cnt  = cact ? g_pcnt[cidx] : 0u;     // carry-free packed halves
    u32 incl = cnt;
#pragma unroll
    for (int s = 1; s < 32; s <<= 1) {
        u32 n = __shfl_up_sync(0xFFFFFFFFu, incl, s);
        if (lane >= s) incl += n;
    }
    if (lane == 31) s_wsum[wid] = incl;
    __syncthreads();
    if (wid == 0) {
        u32 w = (lane < 8) ? s_wsum[lane] : 0u;
#pragma unroll
        for (int s = 1; s < 8; s <<= 1) {
            u32 n = __shfl_up_sync(0xFFFFFFFFu, w, s);
            if (lane >= s) w += n;
        }
        if (lane < 8) s_wsum[lane] = w;             // inclusive warp prefixes
    }
    __syncthreads();
    const u32 wbase = (wid > 0) ? s_wsum[wid - 1] : 0u;
    const u32 excl  = wbase + incl - cnt;           // packed exclusive prefix
    if (tid == NTHR - 1) g_part[blockIdx.x] = wbase + incl;  // packed CTA total
    grid_bar(sense);                                // GB2

    // ---- P2b: packed global offset (sum of parts < my CTA), publish CSR ----
    if (wid == 0) {
        u32 acc0 = 0u;
#pragma unroll
        for (int k = 0; k < NCTA / 32; k++) {
            int idx = k * 32 + lane;
            u32 pv = g_part[idx];
            if (idx < blockIdx.x) acc0 += pv;
        }
#pragma unroll
        for (int s = 16; s > 0; s >>= 1)
            acc0 += __shfl_xor_sync(0xFFFFFFFFu, acc0, s);
        if (lane == 0) s_off = acc0;
    }
    __syncthreads();
    if (cact) {
        u32 pk = s_off + excl;                      // packed starts
        int s0 = (int)(pk & 0xFFFFu), s1 = (int)(pk >> 16);
        g_starts[0][cidx] = s0;  g_cursor[0][cidx] = s0;
        g_starts[1][cidx] = s1;  g_cursor[1][cidx] = s1;
        g_pcnt[cidx] = 0u;                          // re-zero for next replay
    }
    if (t == 0) { g_starts[0][NC] = NPTS; g_starts[1][NC] = NPTS; }
    grid_bar(sense);                                // GB3

    // ---- P3: scatter ----
    if (t < 2 * NPTS) {
        const int cloud = t >> 14, i = t & (NPTS - 1);
        int cell = g_cellid[cloud][i];
        int pos  = atomicAdd(&g_cursor[cloud][cell], 1);
        g_sorted[cloud][pos] = g_pre[cloud][i];
    }
    grid_bar(sense);                                // GB4

    // ---- P4a: 4-lane query, r<=2 only (group-mask shuffles) ----
    const unsigned gmask = 0xFu << (lane & ~3);
    u64 acc = 0ull;
    {
        const int lane4 = t & 3;
        const int qi    = t >> 2;                   // 0 .. 2*NPTS-1
        const int dir   = qi >> 14;
        const int i     = qi & (NPTS - 1);
        const float4* __restrict__ tgt = g_sorted[dir ^ 1];
        const int*    __restrict__ st  = g_starts[dir ^ 1];

        float4 A = g_sorted[dir][i];
        float qx = -0.5f * A.x, qy = -0.5f * A.y, qz = -0.5f * A.z;
        float an = A.w;
        int cx = cell1(qx), cy = cell1(qy), cz = cell1(qz);

        float m = 3.4e38f;
        {   // r = 1 cube: 9 rows over 4 lanes; this lane's <=3 rows scanned
            // INTERLEAVED (3 independent loads in flight, trip count = max len)
            int x0 = max(cx - 1, 0), x1 = min(cx + 1, G - 1);
            int j0 = 0, e0 = 0, j1 = 0, e1 = 0, j2 = 0, e2 = 0;
#pragma unroll
            for (int k0 = 0; k0 < 3; k0++) {
                int k = lane4 + k0 * 4;
                if (k < 9) {
                    int z = cz + k / 3 - 1, y = cy + k % 3 - 1;
                    if ((unsigned)z < G && (unsigned)y < G) {
                        int rb = (z * G + y) * G;
                        int js = __ldg(&st[rb + x0]);
                        int es = __ldg(&st[rb + x1 + 1]);
                        if (k0 == 0) { j0 = js; e0 = es; }
                        else if (k0 == 1) { j1 = js; e1 = es; }
                        else { j2 = js; e2 = es; }
                    }
                }
            }
            while ((j0 < e0) | (j1 < e1) | (j2 < e2)) {
                float4 B0, B1, B2;
                bool a0 = j0 < e0, a1 = j1 < e1, a2 = j2 < e2;
                if (a0) B0 = __ldg(&tgt[j0]);
                if (a1) B1 = __ldg(&tgt[j1]);
                if (a2) B2 = __ldg(&tgt[j2]);
                if (a0) { m = fminf(m, pdist(B0, qx, qy, qz)); j0++; }
                if (a1) { m = fminf(m, pdist(B1, qx, qy, qz)); j1++; }
                if (a2) { m = fminf(m, pdist(B2, qx, qy, qz)); j2++; }
            }
        }
        m = fminf(m, __shfl_xor_sync(gmask, m, 1));
        m = fminf(m, __shfl_xor_sync(gmask, m, 2));

        if (m + an > CS * CS) {                     // group-uniform escalation
            // r = 2 ring: 25 rows; outer rows full x-range, inner rows edges
            int x0 = max(cx - 2, 0), x1 = min(cx + 2, G - 1);
            for (int k = lane4; k < 25; k += 4) {
                int dz = k / 5 - 2, dy = k % 5 - 2;
                int z = cz + dz, y = cy + dy;
                if ((unsigned)z >= G || (unsigned)y >= G) continue;
                int rb = (z * G + y) * G;
                if (max(abs(dz), abs(dy)) == 2) {
                    scan_range(tgt, st[rb + x0], st[rb + x1 + 1], qx, qy, qz, m);
                } else {
                    if (cx - 2 >= 0)
                        scan_range(tgt, st[rb + cx - 2], st[rb + cx - 1], qx, qy, qz, m);
                    if (cx + 2 <= G - 1)
                        scan_range(tgt, st[rb + cx + 2], st[rb + cx + 3], qx, qy, qz, m);
                }
            }
            m = fminf(m, __shfl_xor_sync(gmask, m, 1));
            m = fminf(m, __shfl_xor_sync(gmask, m, 2));
        }

        if (m + an <= 4.0f * CS * CS) {             // certified at r<=2
            if (lane4 == 0) {
                float d = fmaxf(m + an, 0.0f);
                acc = (u64)((double)d * 4294967296.0);
            }
        } else if (lane4 == 0) {                    // enqueue for brute force
            int slot = atomicAdd(&g_fb_cnt, 1);
            g_fb[slot] = qi;
        }
    }
    __syncwarp();
#pragma unroll
    for (int s = 16; s > 0; s >>= 1)
        acc += __shfl_down_sync(0xFFFFFFFFu, acc, s);
    if (lane == 0 && acc) atomicAdd(&g_sum, acc);
    grid_bar(sense);                                // GB5 (last barrier)

    // ---- P4b: cooperative brute force; LAST job's warp finalizes ----
    const int nf = *((volatile int*)&g_fb_cnt);
    const int njobs = nf * WPQ;
    if (njobs > 0) {
        const int gwid = t >> 5;
        for (int job = gwid; job < njobs; job += NWARP) {
            int f = job >> 3, slice = job & (WPQ - 1);
            int qi = g_fb[f];
            int dir = qi >> 14, i = qi & (NPTS - 1);
            float4 A = g_sorted[dir][i];
            float qx = -0.5f * A.x, qy = -0.5f * A.y, qz = -0.5f * A.z;
            float an = A.w;
            const float4* __restrict__ tgt = g_sorted[dir ^ 1];
            float m = 3.4e38f;
            int base = slice * (NPTS / WPQ) + lane;
#pragma unroll 8
            for (int j = 0; j < NPTS / WPQ / 32; j++) {   // 64 coalesced loads
                float4 B = __ldg(&tgt[base + j * 32]);
                m = fminf(m, pdist(B, qx, qy, qz));
            }
#pragma unroll
            for (int s = 16; s > 0; s >>= 1)
                m = fminf(m, __shfl_xor_sync(0xFFFFFFFFu, m, s));
            int ticket = 0;
            if (lane == 0) {
                atomicMin(&g_fbmin[f], __float_as_uint(fmaxf(m + an, 0.0f)));
                __threadfence();
                ticket = atomicAdd(&g_fb_done, 1) + 1;    // jobs completed
            }
            ticket = __shfl_sync(0xFFFFFFFFu, ticket, 0);
            if (ticket == njobs) {                        // this warp is last
                __threadfence();
                u64 a2 = 0ull;
                for (int f2 = lane; f2 < nf; f2 += 32)
                    a2 += (u64)((double)__uint_as_float(
                              *((volatile u32*)&g_fbmin[f2])) * 4294967296.0);
#pragma unroll
                for (int s = 16; s > 0; s >>= 1)
                    a2 += __shfl_down_sync(0xFFFFFFFFu, a2, s);
                if (lane == 0) {
                    u64 tot = atomicAdd(&g_sum, a2) + a2;
                    double sd = (double)tot * (1.0 / 4294967296.0);
                    out[0] = (float)(sd / (double)NPTS);  // mean1 + mean2
                    g_sum = 0ull; g_fb_cnt = 0; g_fb_done = 0;
                    __threadfence();
                }
            }
        }
    } else if (t == 0) {                            // no fallback: finalize now
        u64 tot = atomicAdd(&g_sum, 0ull);
        double sd = (double)tot * (1.0 / 4294967296.0);
        out[0] = (float)(sd / (double)NPTS);
        g_sum = 0ull; g_fb_cnt = 0; g_fb_done = 0;
        __threadfence();
    }
}

extern "C" void kernel_launch(void* const* d_in, const int* in_sizes, int n_in,
                              void* d_out, int out_size) {
    const float* gt  = (const float*)d_in[0];
    const float* gen = (const float*)d_in[1];
    float* out = (float*)d_out;
    cd_fused_kernel<<<NCTA, NTHR>>>(gt, gen, out);
}